// round 14
// baseline (speedup 1.0000x reference)
#include <cuda_runtime.h>
#include <cstdint>

// Dims: B=8, C=1024, T=512, HW=49, D=128, window=101, out_dim=128.

__device__ float g_xm  [8u * 1024u * 512u];  // [B, C, T] spatial means (16.8 MB)
__device__ float g_part[8u * 4096u * 128u];  // [ksplit][b*T+t][d] GEMM partials
__device__ float g_y   [4096u * 128u];       // [B*T, 128] normalized projections

// Packed fp32x2 FMA (sm_100+): d = a*b + d per 32-bit half. FFMA2 in SASS.
__device__ __forceinline__ void fma2(unsigned long long& d,
                                     unsigned long long a,
                                     unsigned long long b) {
    asm("fma.rn.f32x2 %0, %1, %2, %0;" : "+l"(d) : "l"(a), "l"(b));
}
__device__ __forceinline__ unsigned long long bcast2(float x) {
    unsigned long long r;
    unsigned int u = __float_as_uint(x);
    asm("mov.b64 %0, {%1, %1};" : "=l"(r) : "r"(u));
    return r;
}
__device__ __forceinline__ float lo32(unsigned long long v) {
    return __uint_as_float((unsigned int)(v & 0xffffffffull));
}
__device__ __forceinline__ float hi32(unsigned long long v) {
    return __uint_as_float((unsigned int)(v >> 32));
}

#define MBARRIER_INIT(addr, cnt) \
    asm volatile("mbarrier.init.shared.b64 [%0], %1;" \
                 :: "r"(addr), "r"(cnt) : "memory")
#define MBARRIER_EXPECT_TX(addr, bytes) \
    asm volatile("mbarrier.arrive.expect_tx.shared.b64 _, [%0], %1;" \
                 :: "r"(addr), "r"(bytes) : "memory")
#define TMA_BULK_G2S(dst, src, bytes, mbar) \
    asm volatile("cp.async.bulk.shared::cta.global.mbarrier::complete_tx::bytes " \
                 "[%0], [%1], %2, [%3];" \
                 :: "r"(dst), "l"(src), "r"(bytes), "r"(mbar) : "memory")
#define MBARRIER_WAIT(addr, parity) do {                                   \
    asm volatile(                                                          \
        "{\n\t.reg .pred P1;\n\t"                                          \
        "WAIT_LOOP_%=:\n\t"                                                \
        "mbarrier.try_wait.parity.shared.b64 P1, [%0], %1, 0x989680;\n\t"  \
        "@P1 bra.uni WAIT_DONE_%=;\n\t"                                    \
        "bra.uni WAIT_LOOP_%=;\n\t"                                        \
        "WAIT_DONE_%=:\n\t}"                                               \
        :: "r"(addr), "r"(parity) : "memory");                             \
} while (0)

// ---------------------------------------------------------------------------
// Kernel 1: spatial mean over 49 — TMA bulk copy (1 UBLKCP per 25 KB tile,
// mbarrier complete_tx), 2-stage double buffer, 4 tiles per block.
// Reduce: 2 threads per row (24/25 split + shfl pair-combine); stride-49 smem
// reads conflict-free (17r distinct mod 32; h-offset 24 cannot alias).
// ---------------------------------------------------------------------------
#define MEAN_TILE_BYTES 25088

__global__ void __launch_bounds__(256) k_mean(const float* __restrict__ in) {
    __shared__ __align__(16) float s[2][128 * 49];   // 2 x 25088 B
    __shared__ __align__(8) unsigned long long mbar[2];
    int tid = threadIdx.x;
    unsigned int sb[2], mb[2];
    sb[0] = (unsigned int)__cvta_generic_to_shared(s[0]);
    sb[1] = (unsigned int)__cvta_generic_to_shared(s[1]);
    mb[0] = (unsigned int)__cvta_generic_to_shared(&mbar[0]);
    mb[1] = (unsigned int)__cvta_generic_to_shared(&mbar[1]);
    size_t t0 = (size_t)blockIdx.x * 4;

    if (tid == 0) {
        MBARRIER_INIT(mb[0], 1);
        MBARRIER_INIT(mb[1], 1);
    }
    __syncthreads();

    if (tid == 0) {
        MBARRIER_EXPECT_TX(mb[0], MEAN_TILE_BYTES);
        TMA_BULK_G2S(sb[0], in + t0 * 6272, MEAN_TILE_BYTES, mb[0]);
        MBARRIER_EXPECT_TX(mb[1], MEAN_TILE_BYTES);
        TMA_BULK_G2S(sb[1], in + (t0 + 1) * 6272, MEAN_TILE_BYTES, mb[1]);
    }

    int r = tid >> 1;                    // row 0..127
    int h = tid & 1;                     // half: 0 -> 24 elems, 1 -> 25

    #pragma unroll
    for (int i = 0; i < 4; i++) {
        int st = i & 1;
        MBARRIER_WAIT(mb[st], (i >> 1) & 1);

        const float* p = s[st] + r * 49 + h * 24;
        float s0 = 0.f, s1 = 0.f, s2 = 0.f, s3 = 0.f;
        #pragma unroll
        for (int j = 0; j < 24; j += 4) {
            s0 += p[j]; s1 += p[j + 1]; s2 += p[j + 2]; s3 += p[j + 3];
        }
        float acc = (s0 + s1) + (s2 + s3);
        if (h) acc += p[24];
        acc += __shfl_xor_sync(0xffffffffu, acc, 1);   // pair combine
        if (h == 0) g_xm[(t0 + i) * 128 + r] = acc * (1.0f / 49.0f);

        __syncthreads();                 // all reads done before stage reuse
        if (tid == 0 && i + 2 < 4) {
            MBARRIER_EXPECT_TX(mb[st], MEAN_TILE_BYTES);
            TMA_BULK_G2S(sb[st], in + (t0 + i + 2) * 6272,
                         MEAN_TILE_BYTES, mb[st]);
        }
    }
}

// ---------------------------------------------------------------------------
// Kernel 2 (proven): projection GEMM, K-split by 8, packed f32x2 FMA.
// Tile: 16 rows x 128 cols, BK=16; thread = 2 rows x 4 cols. grid 2048.
// ---------------------------------------------------------------------------
__global__ void __launch_bounds__(256) k_proj(const float* __restrict__ pw) {
    __shared__ __align__(16) float As[16][16];
    __shared__ __align__(16) float Bs[16][128];

    int tid = threadIdx.x;
    int tx  = tid & 31;
    int ty  = tid >> 5;
    int bx  = blockIdx.x;
    int z   = bx & 7;                   // K eighth
    int m0  = (bx >> 3) * 16;           // row tile start
    int b   = m0 >> 9;
    int t0  = m0 & 511;
    const float* Abase = g_xm + (size_t)b * 524288 + t0;
    const float4* pw4 = (const float4*)pw;

    int akk = tid >> 4;
    int amm = tid & 15;

    unsigned long long acc00 = 0ull, acc01 = 0ull;
    unsigned long long acc10 = 0ull, acc11 = 0ull;

    int kbeg = z * 128, kend = kbeg + 128;
    for (int k0 = kbeg; k0 < kend; k0 += 16) {
        As[akk][amm] = Abase[(size_t)(k0 + akk) * 512 + amm];
        {
            int i0 = tid, i1 = tid + 256;
            ((float4*)Bs)[i0] = pw4[(size_t)(k0 + (i0 >> 5)) * 32 + (i0 & 31)];
            ((float4*)Bs)[i1] = pw4[(size_t)(k0 + (i1 >> 5)) * 32 + (i1 & 31)];
        }
        __syncthreads();

        #pragma unroll
        for (int k = 0; k < 16; k++) {
            unsigned long long a0 = bcast2(As[k][ty * 2 + 0]);
            unsigned long long a1 = bcast2(As[k][ty * 2 + 1]);
            const ulonglong2* brow = (const ulonglong2*)Bs[k];
            ulonglong2 bb = brow[tx];
            fma2(acc00, a0, bb.x);
            fma2(acc01, a0, bb.y);
            fma2(acc10, a1, bb.x);
            fma2(acc11, a1, bb.y);
        }
        __syncthreads();
    }

    float4 v0 = make_float4(lo32(acc00), hi32(acc00), lo32(acc01), hi32(acc01));
    float4 v1 = make_float4(lo32(acc10), hi32(acc10), lo32(acc11), hi32(acc11));
    size_t row0 = (size_t)(m0 + ty * 2);
    ((float4*)g_part)[((size_t)z * 4096 + row0)     * 32 + tx] = v0;
    ((float4*)g_part)[((size_t)z * 4096 + row0 + 1) * 32 + tx] = v1;
}

// ---------------------------------------------------------------------------
// Epilogue: sum 8 partials + bias, L2 normalize, write g_y.
// ---------------------------------------------------------------------------
__global__ void __launch_bounds__(256) k_norm(const float* __restrict__ pb) {
    int tid  = threadIdx.x;
    int lane = tid & 31;
    int row  = (blockIdx.x * 256 + tid) >> 5;

    const float4* part4 = (const float4*)g_part;
    float4 v = ((const float4*)pb)[lane];
    #pragma unroll
    for (int z = 0; z < 8; z++) {
        float4 p = part4[((size_t)z * 4096 + row) * 32 + lane];
        v.x += p.x; v.y += p.y; v.z += p.z; v.w += p.w;
    }

    float ss = v.x * v.x + v.y * v.y + v.z * v.z + v.w * v.w;
    #pragma unroll
    for (int o = 16; o; o >>= 1) ss += __shfl_xor_sync(0xffffffffu, ss, o);
    float inv = 1.0f / fmaxf(sqrtf(ss), 1e-12f);
    v.x *= inv; v.y *= inv; v.z *= inv; v.w *= inv;
    ((float4*)g_y)[(size_t)row * 32 + lane] = v;
}

// ---------------------------------------------------------------------------
// Kernel 4 (proven): banded cosine-sim + fc + ReLU — shuffle-free smem tile,
// 512 thr, 32 t's/block. Phase 1: (tloc, wi) 7 accs. Phase 2: 4 t's per warp.
// ---------------------------------------------------------------------------
#define BAND_SMEM_FLOATS (132 * 132 + 32 * 104 + 101 * 128)
#define BAND_SMEM_BYTES  (BAND_SMEM_FLOATS * 4)

__global__ void __launch_bounds__(512) k_band_fc(const float* __restrict__ fw,
                                                 const float* __restrict__ fb,
                                                 float* __restrict__ out) {
    extern __shared__ __align__(16) float dyn[];
    float* ys  = dyn;                        // 132 x 132 (row stride 33 float4)
    float* bd  = dyn + 132 * 132;            // 32 x 104
    float* fws = bd + 32 * 104;              // 101 x 128

    int tid = threadIdx.x;
    int r0  = blockIdx.x * 32;               // first global row of this block
    int lo  = r0 & ~511;                     // batch start
    int hi  = lo + 512;

    const float4* y4   = (const float4*)g_y;
    float4*       ys4  = (float4*)ys;
    const float4* fw4  = (const float4*)fw;
    float4*       fws4 = (float4*)fws;

    // Stage y rows [r0-50, r0+82) with zero fill outside the batch.
    for (int idx = tid; idx < 132 * 32; idx += 512) {
        int rr = idx >> 5, c = idx & 31;
        int gr = r0 - 50 + rr;
        float4 v = make_float4(0.f, 0.f, 0.f, 0.f);
        if (gr >= lo && gr < hi) v = y4[(size_t)gr * 32 + c];
        ys4[rr * 33 + c] = v;
    }
    // Stage fc_w.
    for (int idx = tid; idx < 101 * 32; idx += 512) fws4[idx] = fw4[idx];
    __syncthreads();

    // ---- Phase 1: band dots ----
    {
        int tloc = tid >> 4;                 // 0..31
        int wi   = tid & 15;                 // 0..15
        float acc[7];
        #pragma unroll
        for (int j = 0; j < 7; j++) acc[j] = 0.f;

        const float4* qrow  = ys4 + (50 + tloc) * 33;
        const float4* krow0 = ys4 + tloc * 33;

        #pragma unroll 4
        for (int i = 0; i < 32; i++) {
            float4 q = qrow[i];
            #pragma unroll
            for (int j = 0; j < 7; j++) {
                int w = wi + 16 * j;
                if (w < 101) {
                    float4 k = krow0[w * 33 + i];
                    acc[j] += q.x * k.x + q.y * k.y + q.z * k.z + q.w * k.w;
                }
            }
        }
        #pragma unroll
        for (int j = 0; j < 7; j++) {
            int w = wi + 16 * j;
            if (w < 101) bd[tloc * 104 + w] = acc[j];
        }
    }
    __syncthreads();

    // ---- Phase 2: out[t] = relu(band[t] @ fc_w + fb), 4 t's per warp ----
    if (tid < 256) {
        int g    = tid >> 5;                 // warp 0..7 -> t = 4g..4g+3
        int lane = tid & 31;                 // output float4 index
        float4 a0 = make_float4(0.f, 0.f, 0.f, 0.f);
        float4 a1 = a0, a2 = a0, a3 = a0;
        const float* b0p = bd + (4 * g + 0) * 104;
        const float* b1p = bd + (4 * g + 1) * 104;
        const float* b2p = bd + (4 * g + 2) * 104;
        const float* b3p = bd + (4 * g + 3) * 104;

        for (int w = 0; w < 101; w++) {
            float4 f = fws4[w * 32 + lane];
            float s0 = b0p[w], s1 = b1p[w], s2 = b2p[w], s3 = b3p[w];
            a0.x += s0 * f.x; a0.y += s0 * f.y; a0.z += s0 * f.z; a0.w += s0 * f.w;
            a1.x += s1 * f.x; a1.y += s1 * f.y; a1.z += s1 * f.z; a1.w += s1 * f.w;
            a2.x += s2 * f.x; a2.y += s2 * f.y; a2.z += s2 * f.z; a2.w += s2 * f.w;
            a3.x += s3 * f.x; a3.y += s3 * f.y; a3.z += s3 * f.z; a3.w += s3 * f.w;
        }

        float4 bias = ((const float4*)fb)[lane];
        float4* out4 = (float4*)out;
        float4 r;
        r.x = fmaxf(a0.x + bias.x, 0.f); r.y = fmaxf(a0.y + bias.y, 0.f);
        r.z = fmaxf(a0.z + bias.z, 0.f); r.w = fmaxf(a0.w + bias.w, 0.f);
        out4[(size_t)(r0 + 4 * g + 0) * 32 + lane] = r;
        r.x = fmaxf(a1.x + bias.x, 0.f); r.y = fmaxf(a1.y + bias.y, 0.f);
        r.z = fmaxf(a1.z + bias.z, 0.f); r.w = fmaxf(a1.w + bias.w, 0.f);
        out4[(size_t)(r0 + 4 * g + 1) * 32 + lane] = r;
        r.x = fmaxf(a2.x + bias.x, 0.f); r.y = fmaxf(a2.y + bias.y, 0.f);
        r.z = fmaxf(a2.z + bias.z, 0.f); r.w = fmaxf(a2.w + bias.w, 0.f);
        out4[(size_t)(r0 + 4 * g + 2) * 32 + lane] = r;
        r.x = fmaxf(a3.x + bias.x, 0.f); r.y = fmaxf(a3.y + bias.y, 0.f);
        r.z = fmaxf(a3.z + bias.z, 0.f); r.w = fmaxf(a3.w + bias.w, 0.f);
        out4[(size_t)(r0 + 4 * g + 3) * 32 + lane] = r;
    }
}

// ---------------------------------------------------------------------------
extern "C" void kernel_launch(void* const* d_in, const int* in_sizes, int n_in,
                              void* d_out, int out_size) {
    const float* in = (const float*)d_in[0];   // [8,1024,512,7,7]
    const float* pw = (const float*)d_in[1];   // [1024,128]
    const float* pb = (const float*)d_in[2];   // [128]
    const float* fw = (const float*)d_in[3];   // [101,128]
    const float* fb = (const float*)d_in[4];   // [128]
    float* out = (float*)d_out;                // [8,512,128]

    cudaFuncSetAttribute(k_band_fc, cudaFuncAttributeMaxDynamicSharedMemorySize,
                         BAND_SMEM_BYTES);

    k_mean<<<8192, 256>>>(in);                 // TMA bulk, 2-stage, 4 tiles
    k_proj<<<2048, 256>>>(pw);                 // 256 tiles x 8 K-eighths
    k_norm<<<512, 256>>>(pb);                  // partial sum + bias + L2 norm
    k_band_fc<<<128, 512, BAND_SMEM_BYTES>>>(fw, fb, out);  // 32 t's, 512 thr
}